// round 3
// baseline (speedup 1.0000x reference)
#include <cuda_runtime.h>

// CubicalModel_ISM: out[j]     = dot(X[r1(j)], p), r1(j) = inds1[2j]*28 + inds1[2j+1], j in [0,100)
//                   out[100+j] = dot(Y[r2(j)], p)
// Only 200 of 1568 rows are needed. 200 dots x 8 segments = 1600 blocks; the
// last block to finish (ticket counter) sums the partials -> single launch.

#define Q       32768
#define QV      (Q / 4)        // 8192 float4 per row
#define SPLIT   8
#define SEG     (QV / SPLIT)   // 1024 float4 per block
#define NT      256
#define W_DIM   28
#define NDOTS   200
#define NBLK    (NDOTS * SPLIT)

__device__ float g_partial[NBLK];
__device__ unsigned int g_ticket = 0;   // reset to 0 by last block each launch

__global__ __launch_bounds__(NT)
void fused_dot_kernel(const float* __restrict__ X,
                      const float* __restrict__ Y,
                      const float* __restrict__ p,
                      const int*   __restrict__ inds1,
                      const int*   __restrict__ inds2,
                      float* __restrict__ out)
{
    const int b   = blockIdx.x;          // 0..1599
    const int j   = b >> 3;              // dot index 0..199
    const int seg = b & (SPLIT - 1);     // segment 0..7

    const bool second = (j >= 100);
    const int jj = second ? (j - 100) : j;
    const int* __restrict__ inds = second ? inds2 : inds1;
    const float* __restrict__ M  = second ? Y : X;

    const int r = inds[2 * jj] * W_DIM + inds[2 * jj + 1];

    const float4* __restrict__ row = reinterpret_cast<const float4*>(M + (size_t)r * Q);
    const float4* __restrict__ pv  = reinterpret_cast<const float4*>(p);

    const int i0 = seg * SEG + threadIdx.x;

    // Front-batched independent loads: 8x LDG.128 in flight (MLP=8)
    float4 a0 = row[i0];
    float4 a1 = row[i0 +     NT];
    float4 a2 = row[i0 + 2 * NT];
    float4 a3 = row[i0 + 3 * NT];
    float4 b0 = pv [i0];
    float4 b1 = pv [i0 +     NT];
    float4 b2 = pv [i0 + 2 * NT];
    float4 b3 = pv [i0 + 3 * NT];

    float sum = a0.x * b0.x + a0.y * b0.y + a0.z * b0.z + a0.w * b0.w;
    sum += a1.x * b1.x + a1.y * b1.y + a1.z * b1.z + a1.w * b1.w;
    sum += a2.x * b2.x + a2.y * b2.y + a2.z * b2.z + a2.w * b2.w;
    sum += a3.x * b3.x + a3.y * b3.y + a3.z * b3.z + a3.w * b3.w;

    // warp reduce
    #pragma unroll
    for (int off = 16; off > 0; off >>= 1)
        sum += __shfl_xor_sync(0xFFFFFFFFu, sum, off);

    __shared__ float warp_sums[NT / 32];
    __shared__ bool  s_last;
    const int lane = threadIdx.x & 31;
    const int wid  = threadIdx.x >> 5;
    if (lane == 0) warp_sums[wid] = sum;
    __syncthreads();

    if (threadIdx.x == 0) {
        float s = warp_sums[0];
        #pragma unroll
        for (int k = 1; k < NT / 32; k++) s += warp_sums[k];
        g_partial[b] = s;
        __threadfence();                              // publish partial
        unsigned int t = atomicAdd(&g_ticket, 1u);    // draw ticket
        s_last = (t == NBLK - 1);
    }
    __syncthreads();

    if (s_last) {
        // last block: all partials are published (fence+atomic order).
        const int t = threadIdx.x;
        if (t < NDOTS) {
            const volatile float* gp = g_partial + t * SPLIT;
            float s = 0.0f;
            #pragma unroll
            for (int k = 0; k < SPLIT; k++) s += gp[k];
            out[t] = s;
        }
        if (t == 0) g_ticket = 0;   // reset for next graph replay
    }
}

extern "C" void kernel_launch(void* const* d_in, const int* in_sizes, int n_in,
                              void* d_out, int out_size)
{
    const float* X   = (const float*)d_in[0];
    const float* Y   = (const float*)d_in[1];
    const float* p   = (const float*)d_in[2];
    const int* inds1 = (const int*)d_in[3];
    const int* inds2 = (const int*)d_in[4];
    float* out       = (float*)d_out;

    fused_dot_kernel<<<NBLK, NT>>>(X, Y, p, inds1, inds2, out);
}

// round 4
// speedup vs baseline: 1.0182x; 1.0182x over previous
#include <cuda_runtime.h>

// out[j]     = dot(X[r1(j)], p), r1(j) = inds1[2j]*28 + inds1[2j+1], j in [0,100)
// out[100+j] = dot(Y[r2(j)], p)
// Blocks handle 4 dots (same matrix) x 1 segment: p segment loaded once per
// block and reused for 4 rows. 2 matrices x 25 groups x 16 segs = 800 blocks.
// Last block (ticket) folds the 16 partials per dot -> single launch.

#define Q       32768
#define QV      (Q / 4)          // 8192 float4 per row
#define NSEG    16
#define SEGF4   (QV / NSEG)      // 512 float4 per segment
#define NT      256
#define GROUP   4                // dots per block
#define W_DIM   28
#define NDOTS   200
#define NGRP    (NDOTS / GROUP)  // 50
#define NBLK    (NGRP * NSEG)    // 800

__device__ float g_partial[NDOTS * NSEG];
__device__ unsigned int g_ticket = 0;

__device__ __forceinline__ float dot4(float4 a, float4 b) {
    return a.x * b.x + a.y * b.y + a.z * b.z + a.w * b.w;
}

__global__ __launch_bounds__(NT)
void fused_dot4_kernel(const float* __restrict__ X,
                       const float* __restrict__ Y,
                       const float* __restrict__ p,
                       const int*   __restrict__ inds1,
                       const int*   __restrict__ inds2,
                       float* __restrict__ out)
{
    const int b   = blockIdx.x;            // 0..799
    const int grp = b >> 4;                // 0..49
    const int s   = b & (NSEG - 1);        // 0..15

    const bool second = (grp >= NGRP / 2);          // groups 25..49 -> Y
    const int g = second ? (grp - NGRP / 2) : grp;  // 0..24 within matrix
    const int* __restrict__ inds = second ? inds2 : inds1;
    const float* __restrict__ M  = second ? Y : X;

    // 4 row pointers for this group's dots
    const float4* row[GROUP];
    #pragma unroll
    for (int k = 0; k < GROUP; k++) {
        const int jj = g * GROUP + k;
        const int r = inds[2 * jj] * W_DIM + inds[2 * jj + 1];
        row[k] = reinterpret_cast<const float4*>(M + (size_t)r * Q);
    }
    const float4* __restrict__ pv = reinterpret_cast<const float4*>(p);

    const int i0 = s * SEGF4 + threadIdx.x;
    const int i1 = i0 + NT;

    // p segment: loaded ONCE, reused for 4 rows
    const float4 p0 = pv[i0];
    const float4 p1 = pv[i1];

    float sum[GROUP];
    #pragma unroll
    for (int k = 0; k < GROUP; k++) {
        float4 a0 = row[k][i0];
        float4 a1 = row[k][i1];
        sum[k] = dot4(a0, p0) + dot4(a1, p1);
    }

    // warp reduce 4 sums
    #pragma unroll
    for (int off = 16; off > 0; off >>= 1) {
        #pragma unroll
        for (int k = 0; k < GROUP; k++)
            sum[k] += __shfl_xor_sync(0xFFFFFFFFu, sum[k], off);
    }

    __shared__ float warp_sums[NT / 32][GROUP];
    __shared__ bool  s_last;
    const int lane = threadIdx.x & 31;
    const int wid  = threadIdx.x >> 5;
    if (lane == 0) {
        #pragma unroll
        for (int k = 0; k < GROUP; k++) warp_sums[wid][k] = sum[k];
    }
    __syncthreads();

    // threads 0..3 fold the 8 warps for their dot k
    if (threadIdx.x < GROUP) {
        const int k = threadIdx.x;
        float t = warp_sums[0][k];
        #pragma unroll
        for (int w = 1; w < NT / 32; w++) t += warp_sums[w][k];
        const int dot = (second ? 100 : 0) + g * GROUP + k;
        g_partial[dot * NSEG + s] = t;
    }
    __syncthreads();   // make sure partial writes issued before fence by t0

    if (threadIdx.x == 0) {
        __threadfence();                              // publish partials
        unsigned int t = atomicAdd(&g_ticket, 1u);    // draw ticket
        s_last = (t == NBLK - 1);
    }
    __syncthreads();

    if (s_last) {
        const int t = threadIdx.x;
        if (t < NDOTS) {
            const volatile float* gp = g_partial + t * NSEG;
            float acc = 0.0f;
            #pragma unroll
            for (int k = 0; k < NSEG; k++) acc += gp[k];
            out[t] = acc;
        }
        if (t == 0) g_ticket = 0;   // reset for next graph replay
    }
}

extern "C" void kernel_launch(void* const* d_in, const int* in_sizes, int n_in,
                              void* d_out, int out_size)
{
    const float* X   = (const float*)d_in[0];
    const float* Y   = (const float*)d_in[1];
    const float* p   = (const float*)d_in[2];
    const int* inds1 = (const int*)d_in[3];
    const int* inds2 = (const int*)d_in[4];
    float* out       = (float*)d_out;

    fused_dot4_kernel<<<NBLK, NT>>>(X, Y, p, inds1, inds2, out);
}